// round 17
// baseline (speedup 1.0000x reference)
#include <cuda_runtime.h>

#define NF      26
#define EMB     128
#define ROW_IN  (NF * EMB)               // 3328
#define NPAIR   325                      // 26*25/2
#define DENSE   128
#define ROW_OUT (ROW_IN + NPAIR + DENSE) // 3781
#define NB      11                       // ceil(325/32)

typedef unsigned long long ull;

// compile-time pair decode: p in [0,325) -> (f,g), f<g, row-major upper triangle
__host__ __device__ constexpr int pf_(int p) {
    int f = 0, c = NF - 1;
    while (p >= c) { p -= c; f++; c--; }
    return f;
}
__host__ __device__ constexpr int pg_(int p) {
    int f = 0, c = NF - 1;
    while (p >= c) { p -= c; f++; c--; }
    return f + 1 + p;
}

__device__ __forceinline__ ull pack2(float lo, float hi) {
    ull r;
    asm("mov.b64 %0, {%1, %2};" : "=l"(r) : "f"(lo), "f"(hi));
    return r;
}
__device__ __forceinline__ float lo32(ull v) { return __uint_as_float((unsigned)v); }
__device__ __forceinline__ float hi32(ull v) { return __uint_as_float((unsigned)(v >> 32)); }

// 4-element lane-local dot via packed f32x2 (FFMA2 path; ptxas never auto-fuses)
__device__ __forceinline__ float dot4(ull a01, ull a23, ull b01, ull b23) {
    ull p;
    asm("mul.rn.f32x2 %0, %1, %2;" : "=l"(p) : "l"(a01), "l"(b01));
    asm("fma.rn.f32x2 %0, %1, %2, %0;" : "+l"(p) : "l"(a23), "l"(b23));
    return lo32(p) + hi32(p);
}

// ---- static product fill for batch B, slot I ----
template<int B, int I>
__device__ __forceinline__ void batch_prods(const ull (&A01)[NF], const ull (&A23)[NF],
                                            float (&vals)[32])
{
    constexpr int p = B * 32 + I;
    if constexpr (p < NPAIR) {
        constexpr int f = pf_(p);
        constexpr int g = pg_(p);
        vals[I] = dot4(A01[f], A23[f], A01[g], A23[g]);
    } else {
        vals[I] = 0.f;
    }
    if constexpr (I + 1 < 32) batch_prods<B, I + 1>(A01, A23, vals);
}

// ---- two interleaved 32-output butterflies (2x chain ILP) ----
__device__ __forceinline__ void butterfly2(float (&u)[32], float (&v)[32], int lane) {
    #pragma unroll
    for (int m = 16; m >= 1; m >>= 1) {
        const bool hi = (lane & m) != 0;
        #pragma unroll
        for (int i = 0; i < m; i++) {
            float su = hi ? u[i]     : u[i + m];
            float ku = hi ? u[i + m] : u[i];
            float sv = hi ? v[i]     : v[i + m];
            float kv = hi ? v[i + m] : v[i];
            float ru = __shfl_xor_sync(0xFFFFFFFFu, su, m);
            float rv = __shfl_xor_sync(0xFFFFFFFFu, sv, m);
            u[i] = ku + ru;
            v[i] = kv + rv;
        }
    }
}

__device__ __forceinline__ void butterfly1(float (&u)[32], int lane) {
    #pragma unroll
    for (int m = 16; m >= 1; m >>= 1) {
        const bool hi = (lane & m) != 0;
        #pragma unroll
        for (int i = 0; i < m; i++) {
            float su = hi ? u[i]     : u[i + m];
            float ku = hi ? u[i + m] : u[i];
            u[i] = ku + __shfl_xor_sync(0xFFFFFFFFu, su, m);
        }
    }
}

template<int B0, int B1>
__device__ __forceinline__ void do_pair(const ull (&A01)[NF], const ull (&A23)[NF],
                                        float* __restrict__ orow, int lane)
{
    float u[32], v[32];
    batch_prods<B0, 0>(A01, A23, u);
    batch_prods<B1, 0>(A01, A23, v);
    butterfly2(u, v, lane);
    const int i0 = B0 * 32 + lane;
    const int i1 = B1 * 32 + lane;
    if (i0 < NPAIR) orow[ROW_IN + i0] = u[0];
    if (i1 < NPAIR) orow[ROW_IN + i1] = v[0];
}

template<int B>
__device__ __forceinline__ void do_one(const ull (&A01)[NF], const ull (&A23)[NF],
                                       float* __restrict__ orow, int lane)
{
    float u[32];
    batch_prods<B, 0>(A01, A23, u);
    butterfly1(u, lane);
    const int i0 = B * 32 + lane;
    if (i0 < NPAIR) orow[ROW_IN + i0] = u[0];
}

__global__ __launch_bounds__(64)
void fi_kernel(const float* __restrict__ sparse,
               const float* __restrict__ dense,
               float* __restrict__ out)
{
    const int warp = threadIdx.x >> 5;
    const int lane = threadIdx.x & 31;
    const int r    = blockIdx.x;

    // lane l owns elems {l, l+32, l+64, l+96} of every feature (stride-1 mem ops)
    ull A01[NF], A23[NF];
    const float* __restrict__ in = sparse + (size_t)r * ROW_IN + lane;
    float* __restrict__ orow = out + (size_t)r * ROW_OUT;

    #pragma unroll
    for (int f = 0; f < NF; f++) {
        float x0 = in[f * EMB];
        float x1 = in[f * EMB + 32];
        float x2 = in[f * EMB + 64];
        float x3 = in[f * EMB + 96];
        A01[f] = pack2(x0, x1);
        A23[f] = pack2(x2, x3);
    }

    if (warp == 0) {
        // passthrough: features 0..14 + dense (heavier stores, lighter gram)
        #pragma unroll
        for (int f = 0; f < 15; f++) {
            orow[f * EMB + lane]      = lo32(A01[f]);
            orow[f * EMB + 32 + lane] = hi32(A01[f]);
            orow[f * EMB + 64 + lane] = lo32(A23[f]);
            orow[f * EMB + 96 + lane] = hi32(A23[f]);
        }
        {
            const float* __restrict__ dr = dense + (size_t)r * DENSE + lane;
            float* __restrict__ dout = orow + ROW_IN + NPAIR + lane;
            dout[0]  = dr[0];
            dout[32] = dr[32];
            dout[64] = dr[64];
            dout[96] = dr[96];
        }
        do_pair<0, 1>(A01, A23, orow, lane);
        do_pair<2, 3>(A01, A23, orow, lane);
        do_one<4>(A01, A23, orow, lane);
    } else {
        // passthrough: features 15..25 (lighter stores, heavier gram)
        #pragma unroll
        for (int f = 15; f < NF; f++) {
            orow[f * EMB + lane]      = lo32(A01[f]);
            orow[f * EMB + 32 + lane] = hi32(A01[f]);
            orow[f * EMB + 64 + lane] = lo32(A23[f]);
            orow[f * EMB + 96 + lane] = hi32(A23[f]);
        }
        do_pair<5, 6>(A01, A23, orow, lane);
        do_pair<7, 8>(A01, A23, orow, lane);
        do_pair<9, 10>(A01, A23, orow, lane);
    }
}

extern "C" void kernel_launch(void* const* d_in, const int* in_sizes, int n_in,
                              void* d_out, int out_size)
{
    const float* sparse = (const float*)d_in[0];
    const float* dense  = (const float*)d_in[1];
    float* out = (float*)d_out;

    const int batch = in_sizes[0] / ROW_IN;          // 16384
    fi_kernel<<<batch, 64>>>(sparse, dense, out);
}